// round 1
// baseline (speedup 1.0000x reference)
#include <cuda_runtime.h>

#define NN 50000
#define NE 200000
#define ND 32
#define ED 16
#define HD 32
#define OD 32
#define NCOL 1024            // HD*OD
#define EPSV 1e-5f
#define SLOPE 0.01f

#define NWARP 8
#define BLOCK 256
#define EGRID 148

// folded weights (BN absorbed)
__device__ float g_W2f[HD * NCOL];   // [k][c] row-major, c = i*32+o
__device__ float g_b2f[NCOL];
__device__ float g_W1f[ED * HD];     // [d][c]
__device__ float g_b1f[HD];
__device__ int   g_is64;

// ---------------------------------------------------------------------------
// Fold BN into linear weights; detect edge_index dtype (int32 vs int64).
// ---------------------------------------------------------------------------
__global__ void fold_kernel(const float* __restrict__ W1, const float* __restrict__ b1,
                            const float* __restrict__ g1, const float* __restrict__ be1,
                            const float* __restrict__ m1, const float* __restrict__ v1,
                            const float* __restrict__ W2, const float* __restrict__ b2,
                            const float* __restrict__ g2, const float* __restrict__ be2,
                            const float* __restrict__ m2, const float* __restrict__ v2,
                            const int* __restrict__ ei32)
{
    int c = blockIdx.x * blockDim.x + threadIdx.x;
    if (c < NCOL) {
        float s = g2[c] * rsqrtf(v2[c] + EPSV);
        g_b2f[c] = (b2[c] - m2[c]) * s + be2[c];
        #pragma unroll
        for (int k = 0; k < HD; k++)
            g_W2f[k * NCOL + c] = W2[k * NCOL + c] * s;
        if (c < HD) {
            float s1 = g1[c] * rsqrtf(v1[c] + EPSV);
            g_b1f[c] = (b1[c] - m1[c]) * s1 + be1[c];
            #pragma unroll
            for (int d = 0; d < ED; d++)
                g_W1f[d * HD + c] = W1[d * HD + c] * s1;
        }
        if (c == 0) {
            // int64 little-endian: high words (odd int32 slots) are all zero
            // (node ids are nonneg < 2^31). 64 samples -> false-pos prob ~0.
            int all0 = 1;
            for (int i = 0; i < 64; i++)
                if (ei32[2 * i + 1] != 0) { all0 = 0; break; }
            g_is64 = all0;
        }
    }
}

// ---------------------------------------------------------------------------
// out[n,:] = bias + x[n,:] @ root    (one warp per node)
// ---------------------------------------------------------------------------
__global__ void init_kernel(const float* __restrict__ x,
                            const float* __restrict__ root,
                            const float* __restrict__ bias,
                            float* __restrict__ out)
{
    __shared__ float root_s[ND * OD];
    __shared__ float bias_s[OD];
    int t = threadIdx.x;
    for (int i = t; i < ND * OD; i += blockDim.x) root_s[i] = root[i];
    if (t < OD) bias_s[t] = bias[t];
    __syncthreads();

    int lane = t & 31, w = t >> 5;
    int n = blockIdx.x * (blockDim.x >> 5) + w;
    if (n >= NN) return;

    float xv = x[n * ND + lane];
    float acc = bias_s[lane];
    #pragma unroll
    for (int i = 0; i < ND; i++)
        acc = fmaf(__shfl_sync(0xffffffffu, xv, i), root_s[i * OD + lane], acc);
    out[n * OD + lane] = acc;
}

// ---------------------------------------------------------------------------
// Fused edge kernel: per edge  h = leaky(ea@W1f+b1f);
//   t[i][o] = leaky(h@W2f[:,i*32+o] + b2f);  msg[o] = sum_i x_j[i]*t[i][o];
//   atomicAdd(out[dst, o], msg[o]).
// One warp handles 4 edges to amortize W2f shared loads (1 LDS : 4 FFMA).
// ---------------------------------------------------------------------------
extern __shared__ float smem[];

__global__ void __launch_bounds__(BLOCK, 1)
edge_kernel(const float* __restrict__ x,
            const int*   __restrict__ ei32,
            const float* __restrict__ edge_attr,
            float* __restrict__ out)
{
    float* W2s = smem;                 // 32768
    float* b2s = W2s + HD * NCOL;      // 1024
    float* W1s = b2s + NCOL;           // 512
    float* b1s = W1s + ED * HD;        // 32
    float* stg = b1s + HD;             // 8 warps * 320

    int tid = threadIdx.x;
    // cooperative smem fill (vectorized)
    {
        const float4* src = (const float4*)g_W2f;
        float4* dst4 = (float4*)W2s;
        for (int i = tid; i < (HD * NCOL) / 4; i += BLOCK) dst4[i] = src[i];
        for (int i = tid; i < NCOL; i += BLOCK) b2s[i] = g_b2f[i];
        for (int i = tid; i < ED * HD; i += BLOCK) W1s[i] = g_W1f[i];
        if (tid < HD) b1s[tid] = g_b1f[tid];
    }
    __syncthreads();

    int lane = tid & 31, wid = tid >> 5;
    float* ea = stg + wid * 320;       // [4][16]
    float* xj = ea + 64;               // [4][32]
    float* hh = xj + 128;              // [4][32]

    int is64 = g_is64;
    const int ngroups = NE / 4;        // 50000, exact

    for (int g = blockIdx.x * NWARP + wid; g < ngroups; g += (int)gridDim.x * NWARP) {
        int e0 = g * 4;
        int dsts[4];
        #pragma unroll
        for (int e = 0; e < 4; e++) {
            int eid = e0 + e;
            int s = is64 ? ei32[2 * eid]            : ei32[eid];
            int d = is64 ? ei32[2 * (NE + eid)]     : ei32[NE + eid];
            dsts[e] = d;
            xj[e * 32 + lane] = x[s * ND + lane];
            if (lane < ED) ea[e * ED + lane] = edge_attr[eid * ED + lane];
        }
        __syncwarp();

        // first layer (folded BN) + leaky
        #pragma unroll
        for (int e = 0; e < 4; e++) {
            float a = b1s[lane];
            #pragma unroll
            for (int d = 0; d < ED; d++)
                a = fmaf(ea[e * ED + d], W1s[d * HD + lane], a);
            hh[e * 32 + lane] = a >= 0.f ? a : SLOPE * a;
        }
        __syncwarp();

        // second layer into 128 register accumulators t[i][e], lane = o
        float t[32][4];
        #pragma unroll
        for (int i = 0; i < 32; i++) {
            float b = b2s[i * 32 + lane];
            t[i][0] = b; t[i][1] = b; t[i][2] = b; t[i][3] = b;
        }
        for (int k = 0; k < HD; k++) {
            float h0 = hh[k], h1 = hh[32 + k], h2 = hh[64 + k], h3 = hh[96 + k];
            const float* wr = W2s + k * NCOL + lane;
            #pragma unroll
            for (int i = 0; i < 32; i++) {
                float wv = wr[i * 32];
                t[i][0] = fmaf(h0, wv, t[i][0]);
                t[i][1] = fmaf(h1, wv, t[i][1]);
                t[i][2] = fmaf(h2, wv, t[i][2]);
                t[i][3] = fmaf(h3, wv, t[i][3]);
            }
        }

        // leaky + consume with x_j
        float m0 = 0.f, m1 = 0.f, m2 = 0.f, m3 = 0.f;
        #pragma unroll
        for (int i = 0; i < 32; i++) {
            float v;
            v = t[i][0]; v = v >= 0.f ? v : SLOPE * v; m0 = fmaf(xj[i],       v, m0);
            v = t[i][1]; v = v >= 0.f ? v : SLOPE * v; m1 = fmaf(xj[32 + i],  v, m1);
            v = t[i][2]; v = v >= 0.f ? v : SLOPE * v; m2 = fmaf(xj[64 + i],  v, m2);
            v = t[i][3]; v = v >= 0.f ? v : SLOPE * v; m3 = fmaf(xj[96 + i],  v, m3);
        }

        atomicAdd(&out[dsts[0] * OD + lane], m0);
        atomicAdd(&out[dsts[1] * OD + lane], m1);
        atomicAdd(&out[dsts[2] * OD + lane], m2);
        atomicAdd(&out[dsts[3] * OD + lane], m3);
        __syncwarp();   // staging reuse next iteration
    }
}

// ---------------------------------------------------------------------------
extern "C" void kernel_launch(void* const* d_in, const int* in_sizes, int n_in,
                              void* d_out, int out_size)
{
    const float* x    = (const float*)d_in[0];
    const int*   ei   = (const int*)d_in[1];     // int32 view; dtype detected on device
    const float* ea   = (const float*)d_in[2];
    // d_in[3] = batch (unused)
    const float* W1   = (const float*)d_in[4];
    const float* b1   = (const float*)d_in[5];
    const float* g1   = (const float*)d_in[6];
    const float* be1  = (const float*)d_in[7];
    const float* m1   = (const float*)d_in[8];
    const float* v1   = (const float*)d_in[9];
    const float* W2   = (const float*)d_in[10];
    const float* b2   = (const float*)d_in[11];
    const float* g2   = (const float*)d_in[12];
    const float* be2  = (const float*)d_in[13];
    const float* m2   = (const float*)d_in[14];
    const float* v2   = (const float*)d_in[15];
    const float* root = (const float*)d_in[16];
    const float* bias = (const float*)d_in[17];
    float* out = (float*)d_out;

    const int smem_bytes = (HD * NCOL + NCOL + ED * HD + HD + NWARP * 320) * (int)sizeof(float);
    cudaFuncSetAttribute(edge_kernel, cudaFuncAttributeMaxDynamicSharedMemorySize, smem_bytes);

    fold_kernel<<<1, 1024>>>(W1, b1, g1, be1, m1, v1, W2, b2, g2, be2, m2, v2, ei);
    init_kernel<<<(NN + 7) / 8, BLOCK>>>(x, root, bias, out);
    edge_kernel<<<EGRID, BLOCK, smem_bytes>>>(x, ei, ea, out);
}